// round 2
// baseline (speedup 1.0000x reference)
#include <cuda_runtime.h>
#include <math.h>

// Problem dims
#define Bn 16384
#define Kf 3
#define Fn 10
#define Dn 128
#define Hn 64
#define Tn 11

// Scratch (device globals: allocation-free rule)
__device__ float g_WihT[6 * 4 * 128 * 64];   // [kd][type][kc][hid]
__device__ float g_WhhT[6 * 4 * 64 * 64];    // [kd][type][kc][hid]
__device__ float g_embeds[Kf * Bn * Dn];     // [k][b][d] (fwd cols 0..63, bwd 64..127)

// ---------------------------------------------------------------------------
// Prep: transpose LSTM weights once into [type][kc][hid] layout (coalesced
// consumption by the main kernel). 6 blocks (one per (k,dir)), 256 threads.
// ---------------------------------------------------------------------------
__global__ void prep_kernel(const float* __restrict__ wih,
                            const float* __restrict__ whh) {
    const int kd  = blockIdx.x;
    const int tid = threadIdx.x;

    const float* W  = wih + kd * 256 * 128;
    float* dst      = g_WihT + kd * 32768;
    for (int i = tid; i < 32768; i += 256) {
        int hid  = i & 63;
        int r    = i >> 6;          // r = type*128 + kc
        int kc   = r & 127;
        int type = r >> 7;
        dst[i] = W[(type * 64 + hid) * 128 + kc];
    }

    const float* Wh = whh + kd * 256 * 64;
    float* dsth     = g_WhhT + kd * 16384;
    for (int i = tid; i < 16384; i += 256) {
        int hid  = i & 63;
        int r    = i >> 6;          // r = type*64 + kc
        int kc   = r & 63;
        int type = r >> 6;
        dsth[i] = Wh[(type * 64 + hid) * 64 + kc];
    }
}

// ---------------------------------------------------------------------------
// Fused BiLSTM-direction kernel.
// grid = (B/32, 6), block = 256 threads, 1 block/SM (smem-limited).
// Thread (tx = lane 0..31, ty = warp 0..7) owns 4 nodes (ty*4..) x 2 hidden
// (2*tx, 2*tx+1) x 4 gate types.
// ---------------------------------------------------------------------------
#define WIH_F (4 * 128 * 64)
#define WHH_F (4 * 64 * 64)
#define SMEM_FLOATS (WIH_F + WHH_F + 256 + 32 * 128 + 32 * 64)
#define SMEM_BYTES (SMEM_FLOATS * 4)

__device__ __forceinline__ float sigmoidf_(float x) {
    return 1.0f / (1.0f + __expf(-x));
}

__global__ void __launch_bounds__(256, 1) lstm_kernel(
    const float* __restrict__ node,
    const float* __restrict__ neigh,
    const float* __restrict__ bias_all)
{
    extern __shared__ float sm[];
    float* sWih = sm;                  // [type*128+kc][64]
    float* sWhh = sWih + WIH_F;        // [type*64+kc][64]
    float* sB   = sWhh + WHH_F;        // 256
    float* sX   = sB + 256;            // [32][128]
    float* sH   = sX + 32 * 128;       // [32][64]

    const int tid = threadIdx.x;
    const int kd  = blockIdx.y;
    const int k   = kd >> 1;
    const int dir = kd & 1;
    const int n0  = blockIdx.x * 32;

    // Fill smem weights (coalesced reads, stride-1 smem writes)
    {
        const float* gw = g_WihT + kd * 32768;
        for (int i = tid; i < 32768; i += 256) sWih[i] = gw[i];
        const float* gh = g_WhhT + kd * 16384;
        for (int i = tid; i < 16384; i += 256) sWhh[i] = gh[i];
        sB[tid] = bias_all[kd * 256 + tid];
    }
    __syncthreads();

    const int tx = tid & 31;
    const int ty = tid >> 5;

    const float* xrow[4];
    const float* hrow[4];
#pragma unroll
    for (int n = 0; n < 4; ++n) {
        xrow[n] = sX + (ty * 4 + n) * 128;
        hrow[n] = sH + (ty * 4 + n) * 64;
    }
    const float* wb  = sWih + 2 * tx;
    const float* whb = sWhh + 2 * tx;

    const float2 bi = *(const float2*)&sB[0   + 2 * tx];
    const float2 bf = *(const float2*)&sB[64  + 2 * tx];
    const float2 bg = *(const float2*)&sB[128 + 2 * tx];
    const float2 bo = *(const float2*)&sB[192 + 2 * tx];

    float c0[4], c1[4], hs0[4], hs1[4];
#pragma unroll
    for (int n = 0; n < 4; ++n) { c0[n] = c1[n] = hs0[n] = hs1[n] = 0.0f; }

    for (int t = 0; t < Tn; ++t) {
        const int ts = dir ? (Tn - 1 - t) : t;

        // Load x tile (32 nodes x 128 feats) as float4, coalesced
        if (ts == 0) {
            const float4* src = (const float4*)node;
            for (int i = tid; i < 1024; i += 256) {
                int nl = i >> 5;
                int d4 = i & 31;
                ((float4*)sX)[i] = src[(n0 + nl) * 32 + d4];
            }
        } else {
            const int f = ts - 1;
            const float4* src = (const float4*)neigh;
            for (int i = tid; i < 1024; i += 256) {
                int nl = i >> 5;
                int d4 = i & 31;
                ((float4*)sX)[i] = src[(((long)k * Bn + n0 + nl) * Fn + f) * 32 + d4];
            }
        }
        __syncthreads();

        float2 ai[4], af[4], ag[4], ao[4];
#pragma unroll
        for (int n = 0; n < 4; ++n) { ai[n] = bi; af[n] = bf; ag[n] = bg; ao[n] = bo; }

        // x @ Wih^T
#pragma unroll 4
        for (int kc = 0; kc < 128; ++kc) {
            float xv[4];
#pragma unroll
            for (int n = 0; n < 4; ++n) xv[n] = xrow[n][kc];
            const float2 wi = *(const float2*)(wb + kc * 64);
            const float2 wf = *(const float2*)(wb + (128 + kc) * 64);
            const float2 wg = *(const float2*)(wb + (256 + kc) * 64);
            const float2 wo = *(const float2*)(wb + (384 + kc) * 64);
#pragma unroll
            for (int n = 0; n < 4; ++n) {
                ai[n].x += xv[n] * wi.x;  ai[n].y += xv[n] * wi.y;
                af[n].x += xv[n] * wf.x;  af[n].y += xv[n] * wf.y;
                ag[n].x += xv[n] * wg.x;  ag[n].y += xv[n] * wg.y;
                ao[n].x += xv[n] * wo.x;  ao[n].y += xv[n] * wo.y;
            }
        }

        // h @ Whh^T (h == 0 at t == 0)
        if (t > 0) {
#pragma unroll 4
            for (int kc = 0; kc < 64; ++kc) {
                float hv[4];
#pragma unroll
                for (int n = 0; n < 4; ++n) hv[n] = hrow[n][kc];
                const float2 wi = *(const float2*)(whb + kc * 64);
                const float2 wf = *(const float2*)(whb + (64  + kc) * 64);
                const float2 wg = *(const float2*)(whb + (128 + kc) * 64);
                const float2 wo = *(const float2*)(whb + (192 + kc) * 64);
#pragma unroll
                for (int n = 0; n < 4; ++n) {
                    ai[n].x += hv[n] * wi.x;  ai[n].y += hv[n] * wi.y;
                    af[n].x += hv[n] * wf.x;  af[n].y += hv[n] * wf.y;
                    ag[n].x += hv[n] * wg.x;  ag[n].y += hv[n] * wg.y;
                    ao[n].x += hv[n] * wo.x;  ao[n].y += hv[n] * wo.y;
                }
            }
        }
        __syncthreads();   // everyone done reading sX / sH

        // Gate nonlinearities, cell/hidden update, publish h for next step
#pragma unroll
        for (int n = 0; n < 4; ++n) {
            float iv = sigmoidf_(ai[n].x);
            float fv = sigmoidf_(af[n].x);
            float gv = tanhf(ag[n].x);
            float ov = sigmoidf_(ao[n].x);
            c0[n] = fv * c0[n] + iv * gv;
            float h0 = ov * tanhf(c0[n]);
            hs0[n] += h0;

            iv = sigmoidf_(ai[n].y);
            fv = sigmoidf_(af[n].y);
            gv = tanhf(ag[n].y);
            ov = sigmoidf_(ao[n].y);
            c1[n] = fv * c1[n] + iv * gv;
            float h1 = ov * tanhf(c1[n]);
            hs1[n] += h1;

            float2 hp; hp.x = h0; hp.y = h1;
            *(float2*)&sH[(ty * 4 + n) * 64 + 2 * tx] = hp;
        }
        // sH writes are ordered before the next iteration's post-load barrier.
    }

    // Mean over T -> embeds (fwd: cols 0..63, bwd: cols 64..127)
    const float inv = 1.0f / (float)Tn;
#pragma unroll
    for (int n = 0; n < 4; ++n) {
        int gb = n0 + ty * 4 + n;
        float2 e; e.x = hs0[n] * inv; e.y = hs1[n] * inv;
        *(float2*)&g_embeds[((long)k * Bn + gb) * Dn + dir * 64 + 2 * tx] = e;
    }
}

// ---------------------------------------------------------------------------
// Attention over the K+1 = 4 sources (3 fanout embeds + node itself).
// One warp per node; shuffle-reduced dot products; 4-way softmax.
// ---------------------------------------------------------------------------
__global__ void attn_kernel(const float* __restrict__ node,
                            const float* __restrict__ att_w,
                            const float* __restrict__ att_b,
                            float* __restrict__ out)
{
    const int gwarp = (blockIdx.x * blockDim.x + threadIdx.x) >> 5;
    const int lane  = threadIdx.x & 31;
    if (gwarp >= Bn) return;
    const int b = gwarp;

    float nv[4], wn[4], we[4];
#pragma unroll
    for (int j = 0; j < 4; ++j) {
        int d = lane + 32 * j;
        nv[j] = node[(long)b * Dn + d];
        wn[j] = att_w[d];
        we[j] = att_w[Dn + d];
    }

    float dn = 0.0f;
#pragma unroll
    for (int j = 0; j < 4; ++j) dn += wn[j] * nv[j];
#pragma unroll
    for (int off = 16; off > 0; off >>= 1)
        dn += __shfl_xor_sync(0xFFFFFFFFu, dn, off);

    const float ab = att_b[0];

    float ev[4][4];
    float score[4];
#pragma unroll
    for (int l = 0; l < 4; ++l) {
        if (l < 3) {
#pragma unroll
            for (int j = 0; j < 4; ++j)
                ev[l][j] = g_embeds[((long)l * Bn + b) * Dn + lane + 32 * j];
        } else {
#pragma unroll
            for (int j = 0; j < 4; ++j) ev[l][j] = nv[j];
        }
        float de = 0.0f;
#pragma unroll
        for (int j = 0; j < 4; ++j) de += we[j] * ev[l][j];
#pragma unroll
        for (int off = 16; off > 0; off >>= 1)
            de += __shfl_xor_sync(0xFFFFFFFFu, de, off);
        float s = dn + de + ab;
        score[l] = (s > 0.0f) ? s : 0.01f * s;   // leaky_relu slope 0.01
    }

    // softmax over the 4 sources
    float m = score[0];
#pragma unroll
    for (int l = 1; l < 4; ++l) m = fmaxf(m, score[l]);
    float esum = 0.0f;
    float wsc[4];
#pragma unroll
    for (int l = 0; l < 4; ++l) { wsc[l] = __expf(score[l] - m); esum += wsc[l]; }
    const float rs = 1.0f / esum;
#pragma unroll
    for (int l = 0; l < 4; ++l) wsc[l] *= rs;

#pragma unroll
    for (int j = 0; j < 4; ++j) {
        float acc = 0.0f;
#pragma unroll
        for (int l = 0; l < 4; ++l) acc += wsc[l] * ev[l][j];
        out[(long)b * Dn + lane + 32 * j] = acc;
    }
}

// ---------------------------------------------------------------------------
// Launch
// ---------------------------------------------------------------------------
extern "C" void kernel_launch(void* const* d_in, const int* in_sizes, int n_in,
                              void* d_out, int out_size) {
    const float* node   = (const float*)d_in[0];
    const float* neigh  = (const float*)d_in[1];
    const float* wih    = (const float*)d_in[2];
    const float* whh    = (const float*)d_in[3];
    const float* bias   = (const float*)d_in[4];
    const float* att_w  = (const float*)d_in[5];
    const float* att_b  = (const float*)d_in[6];
    float* out = (float*)d_out;

    cudaFuncSetAttribute(lstm_kernel,
                         cudaFuncAttributeMaxDynamicSharedMemorySize, SMEM_BYTES);

    prep_kernel<<<6, 256>>>(wih, whh);
    lstm_kernel<<<dim3(Bn / 32, 6), 256, SMEM_BYTES>>>(node, neigh, bias);
    attn_kernel<<<Bn / 8, 256>>>(node, att_w, att_b, out);
}

// round 4
// speedup vs baseline: 2.3804x; 2.3804x over previous
#include <cuda_runtime.h>
#include <math.h>
#include <stdint.h>

// Problem dims
#define Bn 16384
#define Kf 3
#define Fn 10
#define Dn 128
#define Hn 64
#define Tn 11

// ---------------------------------------------------------------------------
// Device scratch (allocation-free rule)
// ---------------------------------------------------------------------------
__device__ uint32_t g_WihF[6 * 32768];   // [kd][nt(32)][ks(16)][lane(32)][2] tf32 B-frags
__device__ uint32_t g_WhhF[6 * 16384];   // [kd][nt(32)][ks(8)][lane(32)][2]  tf32 B-frags
__device__ float    g_biasR[6 * 256];    // bias in reordered ncol order
__device__ float    g_embeds[Kf * Bn * Dn];  // [k][b][d] (fwd cols 0..63, bwd 64..127)

// ---------------------------------------------------------------------------
// Helpers
// ---------------------------------------------------------------------------
__device__ __forceinline__ uint32_t to_tf32(float f) {
    uint32_t u;
    asm("cvt.rna.tf32.f32 %0, %1;" : "=r"(u) : "f"(f));
    return u;
}
__device__ __forceinline__ float tanh_fast(float x) {
    float y;
    asm("tanh.approx.f32 %0, %1;" : "=f"(y) : "f"(x));
    return y;
}
__device__ __forceinline__ float sigf(float x) {
    return 1.0f / (1.0f + __expf(-x));   // MUFU.EX2 + RCP, near-exact
}
__device__ __forceinline__ void mma_tf32(float* d, const uint32_t* a,
                                         uint32_t b0, uint32_t b1) {
    asm volatile(
        "mma.sync.aligned.m16n8k8.row.col.f32.tf32.tf32.f32 "
        "{%0,%1,%2,%3}, {%4,%5,%6,%7}, {%8,%9}, {%0,%1,%2,%3};"
        : "+f"(d[0]), "+f"(d[1]), "+f"(d[2]), "+f"(d[3])
        : "r"(a[0]), "r"(a[1]), "r"(a[2]), "r"(a[3]), "r"(b0), "r"(b1));
}

// Reordered output column -> original gate row.
// ncol = (hid>>3)*32 + gate*8 + (hid&7)
__device__ __forceinline__ int orig_row(int ncol) {
    int a    = ncol >> 5;
    int gate = (ncol >> 3) & 3;
    int hid  = a * 8 + (ncol & 7);
    return gate * 64 + hid;
}

// ---------------------------------------------------------------------------
// Prep: pack weights into per-lane tf32 mma B-fragment order; reorder bias.
// 6 blocks (one per (k,dir)), 256 threads.
// ---------------------------------------------------------------------------
__global__ void prep_kernel(const float* __restrict__ wih,
                            const float* __restrict__ whh,
                            const float* __restrict__ bias) {
    const int kd  = blockIdx.x;
    const int tid = threadIdx.x;

    // Wih: [256 orig rows][128]  ->  frag[nt][ks][lane][e]
    for (int i = tid; i < 32768; i += 256) {
        int e    = i & 1;
        int lane = (i >> 1) & 31;
        int ks   = (i >> 6) & 15;
        int nt   = i >> 10;
        int ncol = nt * 8 + (lane >> 2);
        int kidx = ks * 8 + (lane & 3) + e * 4;
        float v  = wih[kd * 32768 + orig_row(ncol) * 128 + kidx];
        g_WihF[kd * 32768 + i] = to_tf32(v);
    }
    // Whh: [256][64] -> frag[nt][ks(8)][lane][e]
    for (int i = tid; i < 16384; i += 256) {
        int e    = i & 1;
        int lane = (i >> 1) & 31;
        int ks   = (i >> 6) & 7;
        int nt   = i >> 9;
        int ncol = nt * 8 + (lane >> 2);
        int kidx = ks * 8 + (lane & 3) + e * 4;
        float v  = whh[kd * 16384 + orig_row(ncol) * 64 + kidx];
        g_WhhF[kd * 16384 + i] = to_tf32(v);
    }
    if (tid < 256)
        g_biasR[kd * 256 + tid] = bias[kd * 256 + orig_row(tid)];
}

// ---------------------------------------------------------------------------
// Fused BiLSTM-direction kernel with tf32 mma.sync.
// grid = (Bn/32, 6), block = 256 (8 warps). Warp w owns hidden group w
// (8 hidden units x 4 gates = n-tiles 4w..4w+3) across both 16-row m-tiles.
// ---------------------------------------------------------------------------
#define XPAD 132   // 132 % 32 == 4 -> conflict-free A-fragment LDS
#define HPAD 68    //  68 % 32 == 4
#define W1_WORDS 32768
#define W2_WORDS 16384
#define SMEM_WORDS (W1_WORDS + W2_WORDS + 256 + 32 * XPAD + 32 * HPAD)
#define SMEM_BYTES (SMEM_WORDS * 4)

__global__ void __launch_bounds__(256, 1) lstm_kernel(
    const float* __restrict__ node,
    const float* __restrict__ neigh)
{
    extern __shared__ uint32_t su[];
    uint32_t* sW1 = su;                         // Wih fragments
    uint32_t* sW2 = su + W1_WORDS;              // Whh fragments
    float*    sB  = (float*)(su + W1_WORDS + W2_WORDS);
    uint32_t* sX  = su + W1_WORDS + W2_WORDS + 256;        // [32][XPAD] tf32
    uint32_t* sH  = sX + 32 * XPAD;                        // [32][HPAD] tf32

    const int tid  = threadIdx.x;
    const int lane = tid & 31;
    const int w    = tid >> 5;
    const int gid  = lane >> 2;
    const int tig  = lane & 3;

    const int kd  = blockIdx.y;
    const int k   = kd >> 1;
    const int dir = kd & 1;
    const int n0  = blockIdx.x * 32;

    // Load weight fragments (contiguous, coalesced)
    {
        const uint4* g1 = (const uint4*)(g_WihF + kd * W1_WORDS);
        uint4* d1 = (uint4*)sW1;
        for (int i = tid; i < W1_WORDS / 4; i += 256) d1[i] = g1[i];
        const uint4* g2 = (const uint4*)(g_WhhF + kd * W2_WORDS);
        uint4* d2 = (uint4*)sW2;
        for (int i = tid; i < W2_WORDS / 4; i += 256) d2[i] = g2[i];
        sB[tid] = g_biasR[kd * 256 + tid];
        for (int i = tid; i < 32 * HPAD; i += 256) sH[i] = 0u;
    }
    __syncthreads();

    // Per-thread bias (col depends only on n) : bb[gate][ch]
    float bb[4][2];
#pragma unroll
    for (int g = 0; g < 4; ++g) {
        int ncol = (w * 4 + g) * 8 + 2 * tig;
        bb[g][0] = sB[ncol];
        bb[g][1] = sB[ncol + 1];
    }

    float acc[2][4][4];          // [m-tile][gate][c0..c3]
    float cst[2][4], hs[2][4];   // cell state / hidden running sum
#pragma unroll
    for (int mt = 0; mt < 2; ++mt)
#pragma unroll
        for (int ci = 0; ci < 4; ++ci) { cst[mt][ci] = 0.0f; hs[mt][ci] = 0.0f; }

    for (int t = 0; t < Tn; ++t) {
        const int ts = dir ? (Tn - 1 - t) : t;

        // Load x tile [32 x 128] -> tf32 smem (row-padded)
        const float* src;
        long rstride;
        if (ts == 0) { src = node + (long)n0 * Dn; rstride = Dn; }
        else {
            src = neigh + (((long)k * Bn + n0) * Fn + (ts - 1)) * Dn;
            rstride = (long)Fn * Dn;
        }
        for (int i = tid; i < 1024; i += 256) {
            int row = i >> 5, c4 = i & 31;
            float4 v = *(const float4*)(src + row * rstride + c4 * 4);
            uint4 o;
            o.x = to_tf32(v.x); o.y = to_tf32(v.y);
            o.z = to_tf32(v.z); o.w = to_tf32(v.w);
            *(uint4*)(sX + row * XPAD + c4 * 4) = o;
        }
        __syncthreads();   // sX ready; prev-step sH writes visible

        // accum <- bias
#pragma unroll
        for (int mt = 0; mt < 2; ++mt)
#pragma unroll
            for (int g = 0; g < 4; ++g) {
                acc[mt][g][0] = bb[g][0]; acc[mt][g][1] = bb[g][1];
                acc[mt][g][2] = bb[g][0]; acc[mt][g][3] = bb[g][1];
            }

        // GEMM1: x[32x128] @ Wih -> 16 k-steps
#pragma unroll
        for (int ks = 0; ks < 16; ++ks) {
            uint32_t a[2][4];
#pragma unroll
            for (int mt = 0; mt < 2; ++mt) {
                int r0 = (mt * 16 + gid) * XPAD + ks * 8 + tig;
                a[mt][0] = sX[r0];
                a[mt][1] = sX[r0 + 8 * XPAD];
                a[mt][2] = sX[r0 + 4];
                a[mt][3] = sX[r0 + 8 * XPAD + 4];
            }
#pragma unroll
            for (int g = 0; g < 4; ++g) {
                int boff = (((w * 4 + g) * 16 + ks) * 32 + lane) * 2;
                uint32_t b0 = sW1[boff], b1 = sW1[boff + 1];
                mma_tf32(acc[0][g], a[0], b0, b1);
                mma_tf32(acc[1][g], a[1], b0, b1);
            }
        }

        // GEMM2: h[32x64] @ Whh -> 8 k-steps (h == 0 at t == 0)
#pragma unroll
        for (int ks = 0; ks < 8; ++ks) {
            uint32_t a[2][4];
#pragma unroll
            for (int mt = 0; mt < 2; ++mt) {
                int r0 = (mt * 16 + gid) * HPAD + ks * 8 + tig;
                a[mt][0] = sH[r0];
                a[mt][1] = sH[r0 + 8 * HPAD];
                a[mt][2] = sH[r0 + 4];
                a[mt][3] = sH[r0 + 8 * HPAD + 4];
            }
#pragma unroll
            for (int g = 0; g < 4; ++g) {
                int boff = (((w * 4 + g) * 8 + ks) * 32 + lane) * 2;
                uint32_t b0 = sW2[boff], b1 = sW2[boff + 1];
                mma_tf32(acc[0][g], a[0], b0, b1);
                mma_tf32(acc[1][g], a[1], b0, b1);
            }
        }
        __syncthreads();   // all warps done reading sX / sH

        // Elementwise gates + h publish
#pragma unroll
        for (int mt = 0; mt < 2; ++mt)
#pragma unroll
            for (int ci = 0; ci < 4; ++ci) {
                float iv = sigf(acc[mt][0][ci]);
                float fv = sigf(acc[mt][1][ci]);
                float gv = tanh_fast(acc[mt][2][ci]);
                float ov = sigf(acc[mt][3][ci]);
                float c  = fv * cst[mt][ci] + iv * gv;
                cst[mt][ci] = c;
                float h  = ov * tanh_fast(c);
                hs[mt][ci] += h;
                int r   = ci >> 1, ch = ci & 1;
                int row = mt * 16 + gid + r * 8;
                int col = w * 8 + 2 * tig + ch;
                sH[row * HPAD + col] = to_tf32(h);
            }
        // next iteration's post-X-load barrier orders these writes
    }

    // Mean over T -> embeds
    const float inv = 1.0f / (float)Tn;
#pragma unroll
    for (int mt = 0; mt < 2; ++mt)
#pragma unroll
        for (int ci = 0; ci < 4; ++ci) {
            int row = n0 + mt * 16 + gid + (ci >> 1) * 8;
            int hid = w * 8 + 2 * tig + (ci & 1);
            g_embeds[((long)k * Bn + row) * Dn + dir * 64 + hid] = hs[mt][ci] * inv;
        }
}

// ---------------------------------------------------------------------------
// Attention over the K+1 = 4 sources. One warp per node.
// ---------------------------------------------------------------------------
__global__ void attn_kernel(const float* __restrict__ node,
                            const float* __restrict__ att_w,
                            const float* __restrict__ att_b,
                            float* __restrict__ out)
{
    const int gwarp = (blockIdx.x * blockDim.x + threadIdx.x) >> 5;
    const int lane  = threadIdx.x & 31;
    if (gwarp >= Bn) return;
    const int b = gwarp;

    float nv[4], wn[4], we[4];
#pragma unroll
    for (int j = 0; j < 4; ++j) {
        int d = lane + 32 * j;
        nv[j] = node[(long)b * Dn + d];
        wn[j] = att_w[d];
        we[j] = att_w[Dn + d];
    }

    float dn = 0.0f;
#pragma unroll
    for (int j = 0; j < 4; ++j) dn += wn[j] * nv[j];
#pragma unroll
    for (int off = 16; off > 0; off >>= 1)
        dn += __shfl_xor_sync(0xFFFFFFFFu, dn, off);

    const float ab = att_b[0];

    float ev[4][4];
    float score[4];
#pragma unroll
    for (int l = 0; l < 4; ++l) {
        if (l < 3) {
#pragma unroll
            for (int j = 0; j < 4; ++j)
                ev[l][j] = g_embeds[((long)l * Bn + b) * Dn + lane + 32 * j];
        } else {
#pragma unroll
            for (int j = 0; j < 4; ++j) ev[l][j] = nv[j];
        }
        float de = 0.0f;
#pragma unroll
        for (int j = 0; j < 4; ++j) de += we[j] * ev[l][j];
#pragma unroll
        for (int off = 16; off > 0; off >>= 1)
            de += __shfl_xor_sync(0xFFFFFFFFu, de, off);
        float s = dn + de + ab;
        score[l] = (s > 0.0f) ? s : 0.01f * s;
    }

    float m = score[0];
#pragma unroll
    for (int l = 1; l < 4; ++l) m = fmaxf(m, score[l]);
    float esum = 0.0f;
    float wsc[4];
#pragma unroll
    for (int l = 0; l < 4; ++l) { wsc[l] = __expf(score[l] - m); esum += wsc[l]; }
    const float rs = 1.0f / esum;
#pragma unroll
    for (int l = 0; l < 4; ++l) wsc[l] *= rs;

#pragma unroll
    for (int j = 0; j < 4; ++j) {
        float acc = 0.0f;
#pragma unroll
        for (int l = 0; l < 4; ++l) acc += wsc[l] * ev[l][j];
        out[(long)b * Dn + lane + 32 * j] = acc;
    }
}

// ---------------------------------------------------------------------------
// Launch
// ---------------------------------------------------------------------------
extern "C" void kernel_launch(void* const* d_in, const int* in_sizes, int n_in,
                              void* d_out, int out_size) {
    const float* node   = (const float*)d_in[0];
    const float* neigh  = (const float*)d_in[1];
    const float* wih    = (const float*)d_in[2];
    const float* whh    = (const float*)d_in[3];
    const float* bias   = (const float*)d_in[4];
    const float* att_w  = (const float*)d_in[5];
    const float* att_b  = (const float*)d_in[6];
    float* out = (float*)d_out;

    cudaFuncSetAttribute(lstm_kernel,
                         cudaFuncAttributeMaxDynamicSharedMemorySize, SMEM_BYTES);

    prep_kernel<<<6, 256>>>(wih, whh, bias);
    lstm_kernel<<<dim3(Bn / 32, 6), 256, SMEM_BYTES>>>(node, neigh);
    attn_kernel<<<Bn / 8, 256>>>(node, att_w, att_b, out);
}